// round 1
// baseline (speedup 1.0000x reference)
#include <cuda_runtime.h>
#include <math.h>

#define B_ 8192
#define D_ 2048
#define C_ 4096
#define K_ 1000

#define BM 128
#define BN 128
#define BK 8

// Scratch (device globals — no allocation allowed)
__device__ float g_act[(size_t)B_ * C_];   // RBF activations (unnormalized)
__device__ float g_rowsum[B_];
__device__ float g_x2[B_];
__device__ float g_c2[C_];

// ---------------------------------------------------------------------------
// Row squared-norm reductions
// ---------------------------------------------------------------------------
__global__ void x2_kernel(const float* __restrict__ X) {
    int row = blockIdx.x;
    const float4* p = reinterpret_cast<const float4*>(X + (size_t)row * D_);
    float s = 0.f;
    for (int i = threadIdx.x; i < D_ / 4; i += blockDim.x) {
        float4 v = p[i];
        s += v.x * v.x + v.y * v.y + v.z * v.z + v.w * v.w;
    }
    #pragma unroll
    for (int o = 16; o; o >>= 1) s += __shfl_xor_sync(0xffffffffu, s, o);
    __shared__ float ws[8];
    if ((threadIdx.x & 31) == 0) ws[threadIdx.x >> 5] = s;
    __syncthreads();
    if (threadIdx.x == 0) {
        float t = 0.f;
        #pragma unroll
        for (int i = 0; i < 8; i++) t += ws[i];
        g_x2[row] = t;
        g_rowsum[row] = 0.f;   // zero the rowsum accumulator here
    }
}

__global__ void c2_kernel(const float* __restrict__ Cen) {
    int row = blockIdx.x;
    const float4* p = reinterpret_cast<const float4*>(Cen + (size_t)row * D_);
    float s = 0.f;
    for (int i = threadIdx.x; i < D_ / 4; i += blockDim.x) {
        float4 v = p[i];
        s += v.x * v.x + v.y * v.y + v.z * v.z + v.w * v.w;
    }
    #pragma unroll
    for (int o = 16; o; o >>= 1) s += __shfl_xor_sync(0xffffffffu, s, o);
    __shared__ float ws[8];
    if ((threadIdx.x & 31) == 0) ws[threadIdx.x >> 5] = s;
    __syncthreads();
    if (threadIdx.x == 0) {
        float t = 0.f;
        #pragma unroll
        for (int i = 0; i < 8; i++) t += ws[i];
        g_c2[row] = t;
    }
}

// ---------------------------------------------------------------------------
// GEMM1 fused with RBF epilogue:
//   dot[b][c] = x[b,:] . centers[c,:]
//   act = exp(-beta[c] * sqrt(max(x2[b] + c2[c] - 2 dot, 0)))
//   g_act <- act ;  g_rowsum[b] += sum_c act
// Classic 128x128x8 SGEMM, 256 threads, 8x8 per thread (4x4 quad split).
// ---------------------------------------------------------------------------
__global__ __launch_bounds__(256) void gemm_rbf_kernel(
    const float* __restrict__ X,
    const float* __restrict__ Cen,
    const float* __restrict__ beta)
{
    __shared__ float As[BK][BM];
    __shared__ float Bs[BK][BN];
    __shared__ float s_rowsum[BM];

    const int bx = blockIdx.x;   // C tile
    const int by = blockIdx.y;   // B tile
    const int tid = threadIdx.x;
    const int tx = tid & 15;
    const int ty = tid >> 4;

    const int arow = tid >> 1;          // 0..127
    const int acol = (tid & 1) * 4;     // 0 or 4

    const float* Aptr = X   + (size_t)(by * BM + arow) * D_ + acol;
    const float* Bptr = Cen + (size_t)(bx * BN + arow) * D_ + acol;

    float acc[8][8];
    #pragma unroll
    for (int i = 0; i < 8; i++)
        #pragma unroll
        for (int j = 0; j < 8; j++) acc[i][j] = 0.f;

    if (tid < BM) s_rowsum[tid] = 0.f;

    for (int k0 = 0; k0 < D_; k0 += BK) {
        float4 a4 = *reinterpret_cast<const float4*>(Aptr + k0);
        float4 b4 = *reinterpret_cast<const float4*>(Bptr + k0);
        __syncthreads();
        As[acol + 0][arow] = a4.x; As[acol + 1][arow] = a4.y;
        As[acol + 2][arow] = a4.z; As[acol + 3][arow] = a4.w;
        Bs[acol + 0][arow] = b4.x; Bs[acol + 1][arow] = b4.y;
        Bs[acol + 2][arow] = b4.z; Bs[acol + 3][arow] = b4.w;
        __syncthreads();
        #pragma unroll
        for (int k = 0; k < BK; k++) {
            float ra[8], rb[8];
            float4 a0 = *reinterpret_cast<const float4*>(&As[k][ty * 4]);
            float4 a1 = *reinterpret_cast<const float4*>(&As[k][64 + ty * 4]);
            float4 b0 = *reinterpret_cast<const float4*>(&Bs[k][tx * 4]);
            float4 b1 = *reinterpret_cast<const float4*>(&Bs[k][64 + tx * 4]);
            ra[0]=a0.x; ra[1]=a0.y; ra[2]=a0.z; ra[3]=a0.w;
            ra[4]=a1.x; ra[5]=a1.y; ra[6]=a1.z; ra[7]=a1.w;
            rb[0]=b0.x; rb[1]=b0.y; rb[2]=b0.z; rb[3]=b0.w;
            rb[4]=b1.x; rb[5]=b1.y; rb[6]=b1.z; rb[7]=b1.w;
            #pragma unroll
            for (int i = 0; i < 8; i++)
                #pragma unroll
                for (int j = 0; j < 8; j++)
                    acc[i][j] += ra[i] * rb[j];
        }
    }

    // ------------- epilogue: RBF + row-sum -------------
    int colg[8];
    float betv[8], c2v[8];
    #pragma unroll
    for (int j = 0; j < 8; j++) {
        int lc = (j < 4) ? (tx * 4 + j) : (64 + tx * 4 + (j - 4));
        colg[j] = bx * BN + lc;
        betv[j] = __ldg(&beta[colg[j]]);
        c2v[j]  = g_c2[colg[j]];
    }
    #pragma unroll
    for (int i = 0; i < 8; i++) {
        int lr = (i < 4) ? (ty * 4 + i) : (64 + ty * 4 + (i - 4));
        int row = by * BM + lr;
        float x2v = g_x2[row];
        float a[8];
        float rsum = 0.f;
        #pragma unroll
        for (int j = 0; j < 8; j++) {
            float sq = x2v + c2v[j] - 2.f * acc[i][j];
            float d = sqrtf(fmaxf(sq, 0.f));
            float v = __expf(-betv[j] * d);
            a[j] = v;
            rsum += v;
        }
        float4 v0 = make_float4(a[0], a[1], a[2], a[3]);
        float4 v1 = make_float4(a[4], a[5], a[6], a[7]);
        *reinterpret_cast<float4*>(&g_act[(size_t)row * C_ + colg[0]]) = v0;
        *reinterpret_cast<float4*>(&g_act[(size_t)row * C_ + colg[4]]) = v1;
        atomicAdd(&s_rowsum[lr], rsum);
    }
    __syncthreads();
    if (tid < BM) atomicAdd(&g_rowsum[by * BM + tid], s_rowsum[tid]);
}

// ---------------------------------------------------------------------------
// GEMM2 fused with normalization + bias:
//   out[b][k] = (act[b,:] . W[k,:]) / rowsum[b] + bias[k]
// Same SGEMM structure; N=1000 bounds-checked (float4 granularity, 1000%4==0).
// ---------------------------------------------------------------------------
__global__ __launch_bounds__(256) void gemm_out_kernel(
    const float* __restrict__ W,
    const float* __restrict__ bias,
    float* __restrict__ out)
{
    __shared__ float As[BK][BM];
    __shared__ float Bs[BK][BN];

    const int bx = blockIdx.x;   // K (class) tile
    const int by = blockIdx.y;   // B tile
    const int tid = threadIdx.x;
    const int tx = tid & 15;
    const int ty = tid >> 4;

    const int arow = tid >> 1;
    const int acol = (tid & 1) * 4;

    const float* Aptr = g_act + (size_t)(by * BM + arow) * C_ + acol;
    const int nrow = bx * BN + arow;             // class index for B tile load
    const bool nvalid = (nrow < K_);
    const float* Bptr = W + (size_t)(nvalid ? nrow : 0) * C_ + acol;

    float acc[8][8];
    #pragma unroll
    for (int i = 0; i < 8; i++)
        #pragma unroll
        for (int j = 0; j < 8; j++) acc[i][j] = 0.f;

    for (int k0 = 0; k0 < C_; k0 += BK) {
        float4 a4 = *reinterpret_cast<const float4*>(Aptr + k0);
        float4 b4 = nvalid ? *reinterpret_cast<const float4*>(Bptr + k0)
                           : make_float4(0.f, 0.f, 0.f, 0.f);
        __syncthreads();
        As[acol + 0][arow] = a4.x; As[acol + 1][arow] = a4.y;
        As[acol + 2][arow] = a4.z; As[acol + 3][arow] = a4.w;
        Bs[acol + 0][arow] = b4.x; Bs[acol + 1][arow] = b4.y;
        Bs[acol + 2][arow] = b4.z; Bs[acol + 3][arow] = b4.w;
        __syncthreads();
        #pragma unroll
        for (int k = 0; k < BK; k++) {
            float ra[8], rb[8];
            float4 a0 = *reinterpret_cast<const float4*>(&As[k][ty * 4]);
            float4 a1 = *reinterpret_cast<const float4*>(&As[k][64 + ty * 4]);
            float4 b0 = *reinterpret_cast<const float4*>(&Bs[k][tx * 4]);
            float4 b1 = *reinterpret_cast<const float4*>(&Bs[k][64 + tx * 4]);
            ra[0]=a0.x; ra[1]=a0.y; ra[2]=a0.z; ra[3]=a0.w;
            ra[4]=a1.x; ra[5]=a1.y; ra[6]=a1.z; ra[7]=a1.w;
            rb[0]=b0.x; rb[1]=b0.y; rb[2]=b0.z; rb[3]=b0.w;
            rb[4]=b1.x; rb[5]=b1.y; rb[6]=b1.z; rb[7]=b1.w;
            #pragma unroll
            for (int i = 0; i < 8; i++)
                #pragma unroll
                for (int j = 0; j < 8; j++)
                    acc[i][j] += ra[i] * rb[j];
        }
    }

    // ------------- epilogue: normalize + bias -------------
    #pragma unroll
    for (int i = 0; i < 8; i++) {
        int lr = (i < 4) ? (ty * 4 + i) : (64 + ty * 4 + (i - 4));
        int row = by * BM + lr;
        float inv = 1.0f / g_rowsum[row];
        #pragma unroll
        for (int jg = 0; jg < 2; jg++) {
            int cbase = bx * BN + jg * 64 + tx * 4;
            if (cbase + 3 < K_) {
                float4 bb = *reinterpret_cast<const float4*>(&bias[cbase]);
                float4 o;
                o.x = acc[i][jg * 4 + 0] * inv + bb.x;
                o.y = acc[i][jg * 4 + 1] * inv + bb.y;
                o.z = acc[i][jg * 4 + 2] * inv + bb.z;
                o.w = acc[i][jg * 4 + 3] * inv + bb.w;
                *reinterpret_cast<float4*>(&out[(size_t)row * K_ + cbase]) = o;
            }
        }
    }
}

// ---------------------------------------------------------------------------
extern "C" void kernel_launch(void* const* d_in, const int* in_sizes, int n_in,
                              void* d_out, int out_size) {
    const float* x       = (const float*)d_in[0];
    const float* centers = (const float*)d_in[1];
    const float* beta    = (const float*)d_in[2];
    const float* W       = (const float*)d_in[3];
    const float* bias    = (const float*)d_in[4];
    float* out = (float*)d_out;

    x2_kernel<<<B_, 256>>>(x);          // also zeroes g_rowsum
    c2_kernel<<<C_, 256>>>(centers);

    dim3 g1(C_ / BN, B_ / BM);          // (32, 64)
    gemm_rbf_kernel<<<g1, 256>>>(x, centers, beta);

    dim3 g2((K_ + BN - 1) / BN, B_ / BM); // (8, 64)
    gemm_out_kernel<<<g2, 256>>>(W, bias, out);
}

// round 3
// speedup vs baseline: 1.5111x; 1.5111x over previous
#include <cuda_runtime.h>
#include <cuda_bf16.h>
#include <stdint.h>
#include <math.h>

#define B_ 8192
#define D_ 2048
#define C_ 4096
#define K_ 1000
#define KPAD_ 1024

#define PADK 40                 // smem row length in bf16 (32 data + 8 pad)
#define ROWB (PADK * 2)         // 80 bytes per row
#define PART_BYTES (128 * ROWB) // 10240
#define BUF_BYTES (4 * PART_BYTES)
#define GEMM_SMEM (2 * BUF_BYTES)

// ---------------------------------------------------------------------------
// Device scratch (no allocation allowed -> __device__ globals)
// ---------------------------------------------------------------------------
__device__ __align__(128) __nv_bfloat16 g_xhi[(size_t)B_ * D_], g_xlo[(size_t)B_ * D_];
__device__ __align__(128) __nv_bfloat16 g_chi[(size_t)C_ * D_], g_clo[(size_t)C_ * D_];
__device__ __align__(128) __nv_bfloat16 g_Whi[(size_t)KPAD_ * C_], g_Wlo[(size_t)KPAD_ * C_];
__device__ __align__(128) __nv_bfloat16 g_ahi[(size_t)B_ * C_], g_alo[(size_t)B_ * C_];
__device__ float g_x2[B_], g_c2[C_], g_rowsum[B_];

// ---------------------------------------------------------------------------
// PTX helpers (portable sm_80+ only: ldmatrix / mma.sync / cp.async)
// ---------------------------------------------------------------------------
__device__ __forceinline__ uint32_t smem_u32(const void* p) {
    uint32_t a;
    asm("{ .reg .u64 t; cvta.to.shared.u64 t, %1; cvt.u32.u64 %0, t; }"
        : "=r"(a) : "l"(p));
    return a;
}

__device__ __forceinline__ void ldsm_x4(uint32_t& r0, uint32_t& r1, uint32_t& r2,
                                        uint32_t& r3, uint32_t addr) {
    asm volatile("ldmatrix.sync.aligned.m8n8.x4.shared.b16 {%0,%1,%2,%3}, [%4];"
                 : "=r"(r0), "=r"(r1), "=r"(r2), "=r"(r3) : "r"(addr));
}

__device__ __forceinline__ void mma16816(float c[4], const uint32_t a[4],
                                         const uint32_t b[2]) {
    asm volatile(
        "mma.sync.aligned.m16n8k16.row.col.f32.bf16.bf16.f32 "
        "{%0,%1,%2,%3}, {%4,%5,%6,%7}, {%8,%9}, {%0,%1,%2,%3};"
        : "+f"(c[0]), "+f"(c[1]), "+f"(c[2]), "+f"(c[3])
        : "r"(a[0]), "r"(a[1]), "r"(a[2]), "r"(a[3]), "r"(b[0]), "r"(b[1]));
}

__device__ __forceinline__ void cp16(uint32_t dst, const void* src) {
    asm volatile("cp.async.cg.shared.global [%0], [%1], 16;"
                 :: "r"(dst), "l"(src) : "memory");
}
#define CP_COMMIT() asm volatile("cp.async.commit_group;" ::: "memory")
template <int N>
__device__ __forceinline__ void cp_wait() {
    asm volatile("cp.async.wait_group %0;" :: "n"(N) : "memory");
}

// ---------------------------------------------------------------------------
// fp32 -> bf16 hi/lo split kernels
// ---------------------------------------------------------------------------
__global__ void split_kernel(const float* __restrict__ src,
                             __nv_bfloat16* __restrict__ hi,
                             __nv_bfloat16* __restrict__ lo, int n4) {
    int i = blockIdx.x * blockDim.x + threadIdx.x;
    if (i >= n4) return;
    float4 v = reinterpret_cast<const float4*>(src)[i];
    float f[4] = {v.x, v.y, v.z, v.w};
    __nv_bfloat16 h[4], l[4];
    #pragma unroll
    for (int j = 0; j < 4; j++) {
        h[j] = __float2bfloat16(f[j]);
        l[j] = __float2bfloat16(f[j] - __bfloat162float(h[j]));
    }
    *reinterpret_cast<uint2*>(hi + (size_t)i * 4) = *reinterpret_cast<uint2*>(h);
    *reinterpret_cast<uint2*>(lo + (size_t)i * 4) = *reinterpret_cast<uint2*>(l);
}

__global__ void splitW_kernel(const float* __restrict__ W) {
    int i = blockIdx.x * blockDim.x + threadIdx.x;   // over KPAD_*C_/4
    if (i >= KPAD_ * C_ / 4) return;
    int r = i >> 10;             // / (C_/4)
    int c0 = (i & 1023) * 4;
    float f[4] = {0.f, 0.f, 0.f, 0.f};
    if (r < K_) {
        float4 v = *reinterpret_cast<const float4*>(W + (size_t)r * C_ + c0);
        f[0] = v.x; f[1] = v.y; f[2] = v.z; f[3] = v.w;
    }
    __nv_bfloat16 h[4], l[4];
    #pragma unroll
    for (int j = 0; j < 4; j++) {
        h[j] = __float2bfloat16(f[j]);
        l[j] = __float2bfloat16(f[j] - __bfloat162float(h[j]));
    }
    *reinterpret_cast<uint2*>(g_Whi + (size_t)r * C_ + c0) = *reinterpret_cast<uint2*>(h);
    *reinterpret_cast<uint2*>(g_Wlo + (size_t)r * C_ + c0) = *reinterpret_cast<uint2*>(l);
}

// ---------------------------------------------------------------------------
// Row squared-norm reductions (x2 also zeroes rowsum)
// ---------------------------------------------------------------------------
template <int DIM, bool IS_X>
__global__ void norm_kernel(const float* __restrict__ P) {
    int row = blockIdx.x;
    const float4* p = reinterpret_cast<const float4*>(P + (size_t)row * DIM);
    float s = 0.f;
    for (int i = threadIdx.x; i < DIM / 4; i += blockDim.x) {
        float4 v = p[i];
        s += v.x * v.x + v.y * v.y + v.z * v.z + v.w * v.w;
    }
    #pragma unroll
    for (int o = 16; o; o >>= 1) s += __shfl_xor_sync(0xffffffffu, s, o);
    __shared__ float ws[8];
    if ((threadIdx.x & 31) == 0) ws[threadIdx.x >> 5] = s;
    __syncthreads();
    if (threadIdx.x == 0) {
        float t = 0.f;
        #pragma unroll
        for (int i = 0; i < 8; i++) t += ws[i];
        if (IS_X) { g_x2[row] = t; g_rowsum[row] = 0.f; }
        else      { g_c2[row] = t; }
    }
}

// ---------------------------------------------------------------------------
// HMMA GEMM, 128x128 CTA tile, 8 warps (warp tile 64x32), K-chunk 32,
// cp.async double-buffered. 3-pass bf16 hi/lo: D += AhBh + AhBl + AlBh.
// MODE 0: RBF epilogue.  MODE 1: normalize + bias epilogue.
// SMEM buffer layout: [Ahi | Alo | Bhi | Blo], each 128 rows x 40 bf16 (80B).
// ---------------------------------------------------------------------------
template <int KDIM, int MODE>
__global__ __launch_bounds__(256, 1) void gemm_mma_kernel(
    const __nv_bfloat16* __restrict__ Ahi, const __nv_bfloat16* __restrict__ Alo,
    const __nv_bfloat16* __restrict__ Bhi, const __nv_bfloat16* __restrict__ Blo,
    const float* __restrict__ beta, const float* __restrict__ bias,
    float* __restrict__ out)
{
    extern __shared__ char smem[];
    const uint32_t sb = smem_u32(smem);
    const int tid = threadIdx.x;
    const int w = tid >> 5, lane = tid & 31;
    const int warp_m = w >> 2, warp_n = w & 3;
    const int bx = blockIdx.x, by = blockIdx.y;

    // ---- loader assignment: 4 parts x 64 threads, 8 granules (16B) each ----
    const int part = tid >> 6;
    const int l6 = tid & 63;
    const int row0 = l6 >> 2;        // 0..15
    const int gg = l6 & 3;           // 16B granule in 64B row
    const __nv_bfloat16* srcBase =
        (part == 0) ? Ahi : (part == 1) ? Alo : (part == 2) ? Bhi : Blo;
    const int rbase = (part < 2) ? by * 128 : bx * 128;
    const __nv_bfloat16* src0 = srcBase + (size_t)(rbase + row0) * KDIM + gg * 8;
    const uint32_t dst0 = sb + part * PART_BYTES + row0 * ROWB + gg * 16;

    float acc[4][4][4];
    #pragma unroll
    for (int mt = 0; mt < 4; mt++)
        #pragma unroll
        for (int nt = 0; nt < 4; nt++)
            #pragma unroll
            for (int q = 0; q < 4; q++) acc[mt][nt][q] = 0.f;

    constexpr int NCH = KDIM / 32;

    // issue chunk 0
    {
        const __nv_bfloat16* s = src0;
        #pragma unroll
        for (int j = 0; j < 8; j++)
            cp16(dst0 + j * 16 * ROWB, s + (size_t)(j * 16) * KDIM);
        CP_COMMIT();
    }

    // fragment address components (constant across chunks)
    const uint32_t aoff = (uint32_t)(warp_m * 64 + (lane & 15)) * ROWB +
                          (uint32_t)((lane >> 4) << 3) * 2;
    const uint32_t boff = (uint32_t)(warp_n * 32 + (lane & 7) + ((lane >> 4) << 3)) * ROWB +
                          (uint32_t)(lane & 8) * 2;

    for (int c = 0; c < NCH; c++) {
        if (c + 1 < NCH) {
            const __nv_bfloat16* s = src0 + (size_t)(c + 1) * 32;
            const uint32_t d = dst0 + ((c + 1) & 1) * BUF_BYTES;
            #pragma unroll
            for (int j = 0; j < 8; j++)
                cp16(d + j * 16 * ROWB, s + (size_t)(j * 16) * KDIM);
            CP_COMMIT();
            cp_wait<1>();
        } else {
            cp_wait<0>();
        }
        __syncthreads();

        const uint32_t bufb = sb + (c & 1) * BUF_BYTES;
        #pragma unroll
        for (int ks = 0; ks < 2; ks++) {
            const uint32_t kso = ks * 32;   // 16 bf16 = 32 bytes
            uint32_t AH[4][4], AL[4][4], BH[4][2], BL[4][2];
            #pragma unroll
            for (int mt = 0; mt < 4; mt++) {
                ldsm_x4(AH[mt][0], AH[mt][1], AH[mt][2], AH[mt][3],
                        bufb + aoff + kso + mt * 16 * ROWB);
                ldsm_x4(AL[mt][0], AL[mt][1], AL[mt][2], AL[mt][3],
                        bufb + PART_BYTES + aoff + kso + mt * 16 * ROWB);
            }
            #pragma unroll
            for (int np = 0; np < 2; np++) {
                uint32_t r0, r1, r2, r3;
                ldsm_x4(r0, r1, r2, r3,
                        bufb + 2 * PART_BYTES + boff + kso + np * 16 * ROWB);
                BH[np * 2][0] = r0; BH[np * 2][1] = r1;
                BH[np * 2 + 1][0] = r2; BH[np * 2 + 1][1] = r3;
                ldsm_x4(r0, r1, r2, r3,
                        bufb + 3 * PART_BYTES + boff + kso + np * 16 * ROWB);
                BL[np * 2][0] = r0; BL[np * 2][1] = r1;
                BL[np * 2 + 1][0] = r2; BL[np * 2 + 1][1] = r3;
            }
            #pragma unroll
            for (int mt = 0; mt < 4; mt++)
                #pragma unroll
                for (int nt = 0; nt < 4; nt++) {
                    mma16816(acc[mt][nt], AH[mt], BH[nt]);
                    mma16816(acc[mt][nt], AH[mt], BL[nt]);
                    mma16816(acc[mt][nt], AL[mt], BH[nt]);
                }
        }
        __syncthreads();
    }

    // ------------------------------ epilogue -------------------------------
    const int lr = lane >> 2;
    const int lc = (lane & 3) * 2;

    if (MODE == 0) {
        #pragma unroll
        for (int mt = 0; mt < 4; mt++) {
            #pragma unroll
            for (int h = 0; h < 2; h++) {
                const int row = by * 128 + warp_m * 64 + mt * 16 + h * 8 + lr;
                const float x2v = g_x2[row];
                float rsum = 0.f;
                #pragma unroll
                for (int nt = 0; nt < 4; nt++) {
                    const int col = bx * 128 + warp_n * 32 + nt * 8 + lc;
                    const float d0 = acc[mt][nt][h * 2 + 0];
                    const float d1 = acc[mt][nt][h * 2 + 1];
                    float sq0 = x2v + g_c2[col]     - 2.f * d0;
                    float sq1 = x2v + g_c2[col + 1] - 2.f * d1;
                    float v0 = __expf(-beta[col]     * sqrtf(fmaxf(sq0, 0.f)));
                    float v1 = __expf(-beta[col + 1] * sqrtf(fmaxf(sq1, 0.f)));
                    rsum += v0 + v1;
                    __nv_bfloat16 h0 = __float2bfloat16(v0);
                    __nv_bfloat16 h1 = __float2bfloat16(v1);
                    __nv_bfloat16 l0 = __float2bfloat16(v0 - __bfloat162float(h0));
                    __nv_bfloat16 l1 = __float2bfloat16(v1 - __bfloat162float(h1));
                    uint32_t hp = (uint32_t)__bfloat16_as_ushort(h0) |
                                  ((uint32_t)__bfloat16_as_ushort(h1) << 16);
                    uint32_t lp = (uint32_t)__bfloat16_as_ushort(l0) |
                                  ((uint32_t)__bfloat16_as_ushort(l1) << 16);
                    *reinterpret_cast<uint32_t*>(&g_ahi[(size_t)row * C_ + col]) = hp;
                    *reinterpret_cast<uint32_t*>(&g_alo[(size_t)row * C_ + col]) = lp;
                }
                rsum += __shfl_xor_sync(0xffffffffu, rsum, 1);
                rsum += __shfl_xor_sync(0xffffffffu, rsum, 2);
                if ((lane & 3) == 0) atomicAdd(&g_rowsum[row], rsum);
            }
        }
    } else {
        #pragma unroll
        for (int mt = 0; mt < 4; mt++) {
            #pragma unroll
            for (int h = 0; h < 2; h++) {
                const int row = by * 128 + warp_m * 64 + mt * 16 + h * 8 + lr;
                const float inv = 1.0f / g_rowsum[row];
                #pragma unroll
                for (int nt = 0; nt < 4; nt++) {
                    const int col = bx * 128 + warp_n * 32 + nt * 8 + lc;
                    if (col < K_) {
                        float2 bb = *reinterpret_cast<const float2*>(&bias[col]);
                        float2 o;
                        o.x = acc[mt][nt][h * 2 + 0] * inv + bb.x;
                        o.y = acc[mt][nt][h * 2 + 1] * inv + bb.y;
                        *reinterpret_cast<float2*>(&out[(size_t)row * K_ + col]) = o;
                    }
                }
            }
        }
    }
}

// ---------------------------------------------------------------------------
extern "C" void kernel_launch(void* const* d_in, const int* in_sizes, int n_in,
                              void* d_out, int out_size) {
    const float* x       = (const float*)d_in[0];
    const float* centers = (const float*)d_in[1];
    const float* beta    = (const float*)d_in[2];
    const float* W       = (const float*)d_in[3];
    const float* bias    = (const float*)d_in[4];
    float* out = (float*)d_out;

    __nv_bfloat16 *xhi, *xlo, *chi, *clo, *ahi, *alo, *whi, *wlo;
    cudaGetSymbolAddress((void**)&xhi, g_xhi);
    cudaGetSymbolAddress((void**)&xlo, g_xlo);
    cudaGetSymbolAddress((void**)&chi, g_chi);
    cudaGetSymbolAddress((void**)&clo, g_clo);
    cudaGetSymbolAddress((void**)&ahi, g_ahi);
    cudaGetSymbolAddress((void**)&alo, g_alo);
    cudaGetSymbolAddress((void**)&whi, g_Whi);
    cudaGetSymbolAddress((void**)&wlo, g_Wlo);

    cudaFuncSetAttribute(gemm_mma_kernel<D_, 0>,
                         cudaFuncAttributeMaxDynamicSharedMemorySize, GEMM_SMEM);
    cudaFuncSetAttribute(gemm_mma_kernel<C_, 1>,
                         cudaFuncAttributeMaxDynamicSharedMemorySize, GEMM_SMEM);

    {
        int n4 = B_ * D_ / 4;
        split_kernel<<<(n4 + 255) / 256, 256>>>(x, xhi, xlo, n4);
    }
    {
        int n4 = C_ * D_ / 4;
        split_kernel<<<(n4 + 255) / 256, 256>>>(centers, chi, clo, n4);
    }
    {
        int n4 = KPAD_ * C_ / 4;
        splitW_kernel<<<(n4 + 255) / 256, 256>>>(W);
    }
    norm_kernel<D_, true><<<B_, 256>>>(x);
    norm_kernel<D_, false><<<C_, 256>>>(centers);

    dim3 g1(C_ / 128, B_ / 128);            // (32, 64)
    gemm_mma_kernel<D_, 0><<<g1, 256, GEMM_SMEM>>>(xhi, xlo, chi, clo,
                                                   beta, bias, out);

    dim3 g2(KPAD_ / 128, B_ / 128);         // (8, 64)
    gemm_mma_kernel<C_, 1><<<g2, 256, GEMM_SMEM>>>(ahi, alo, whi, wlo,
                                                   beta, bias, out);
}

// round 4
// speedup vs baseline: 1.7358x; 1.1487x over previous
#include <cuda_runtime.h>
#include <cuda_bf16.h>
#include <stdint.h>
#include <math.h>

#define B_ 8192
#define D_ 2048
#define C_ 4096
#define K_ 1000
#define KPAD_ 1024

#define PADK 40                 // smem row length in bf16 (32 data + 8 pad)
#define ROWB (PADK * 2)         // 80 bytes per row
#define PART_BYTES (128 * ROWB) // 10240
#define BUF_BYTES (4 * PART_BYTES)
#define GEMM_SMEM (2 * BUF_BYTES)

// ---------------------------------------------------------------------------
// Device scratch (no allocation allowed -> __device__ globals)
// ---------------------------------------------------------------------------
__device__ __align__(128) __nv_bfloat16 g_xhi[(size_t)B_ * D_], g_xlo[(size_t)B_ * D_];
__device__ __align__(128) __nv_bfloat16 g_chi[(size_t)C_ * D_], g_clo[(size_t)C_ * D_];
__device__ __align__(128) __nv_bfloat16 g_Whi[(size_t)KPAD_ * C_], g_Wlo[(size_t)KPAD_ * C_];
__device__ __align__(128) __nv_bfloat16 g_ahi[(size_t)B_ * C_], g_alo[(size_t)B_ * C_];
__device__ float g_x2[B_], g_c2[C_], g_rowsum[B_];

// ---------------------------------------------------------------------------
// PTX helpers (portable sm_80+: ldmatrix / mma.sync / cp.async)
// ---------------------------------------------------------------------------
__device__ __forceinline__ uint32_t smem_u32(const void* p) {
    uint32_t a;
    asm("{ .reg .u64 t; cvta.to.shared.u64 t, %1; cvt.u32.u64 %0, t; }"
        : "=r"(a) : "l"(p));
    return a;
}

__device__ __forceinline__ void ldsm_x4(uint32_t& r0, uint32_t& r1, uint32_t& r2,
                                        uint32_t& r3, uint32_t addr) {
    asm volatile("ldmatrix.sync.aligned.m8n8.x4.shared.b16 {%0,%1,%2,%3}, [%4];"
                 : "=r"(r0), "=r"(r1), "=r"(r2), "=r"(r3) : "r"(addr));
}

__device__ __forceinline__ void mma16816(float c[4], const uint32_t a[4],
                                         const uint32_t b[2]) {
    asm volatile(
        "mma.sync.aligned.m16n8k16.row.col.f32.bf16.bf16.f32 "
        "{%0,%1,%2,%3}, {%4,%5,%6,%7}, {%8,%9}, {%0,%1,%2,%3};"
        : "+f"(c[0]), "+f"(c[1]), "+f"(c[2]), "+f"(c[3])
        : "r"(a[0]), "r"(a[1]), "r"(a[2]), "r"(a[3]), "r"(b[0]), "r"(b[1]));
}

__device__ __forceinline__ void cp16(uint32_t dst, const void* src) {
    asm volatile("cp.async.cg.shared.global [%0], [%1], 16;"
                 :: "r"(dst), "l"(src) : "memory");
}
#define CP_COMMIT() asm volatile("cp.async.commit_group;" ::: "memory")
template <int N>
__device__ __forceinline__ void cp_wait() {
    asm volatile("cp.async.wait_group %0;" :: "n"(N) : "memory");
}

// ---------------------------------------------------------------------------
// fp32 -> bf16 hi/lo split kernels
// ---------------------------------------------------------------------------
__global__ void split_kernel(const float* __restrict__ src,
                             __nv_bfloat16* __restrict__ hi,
                             __nv_bfloat16* __restrict__ lo, int n4) {
    int i = blockIdx.x * blockDim.x + threadIdx.x;
    if (i >= n4) return;
    float4 v = reinterpret_cast<const float4*>(src)[i];
    float f[4] = {v.x, v.y, v.z, v.w};
    __nv_bfloat16 h[4], l[4];
    #pragma unroll
    for (int j = 0; j < 4; j++) {
        h[j] = __float2bfloat16(f[j]);
        l[j] = __float2bfloat16(f[j] - __bfloat162float(h[j]));
    }
    *reinterpret_cast<uint2*>(hi + (size_t)i * 4) = *reinterpret_cast<uint2*>(h);
    *reinterpret_cast<uint2*>(lo + (size_t)i * 4) = *reinterpret_cast<uint2*>(l);
}

__global__ void splitW_kernel(const float* __restrict__ W) {
    int i = blockIdx.x * blockDim.x + threadIdx.x;   // over KPAD_*C_/4
    if (i >= KPAD_ * C_ / 4) return;
    int r = i >> 10;             // / (C_/4)
    int c0 = (i & 1023) * 4;
    float f[4] = {0.f, 0.f, 0.f, 0.f};
    if (r < K_) {
        float4 v = *reinterpret_cast<const float4*>(W + (size_t)r * C_ + c0);
        f[0] = v.x; f[1] = v.y; f[2] = v.z; f[3] = v.w;
    }
    __nv_bfloat16 h[4], l[4];
    #pragma unroll
    for (int j = 0; j < 4; j++) {
        h[j] = __float2bfloat16(f[j]);
        l[j] = __float2bfloat16(f[j] - __bfloat162float(h[j]));
    }
    *reinterpret_cast<uint2*>(g_Whi + (size_t)r * C_ + c0) = *reinterpret_cast<uint2*>(h);
    *reinterpret_cast<uint2*>(g_Wlo + (size_t)r * C_ + c0) = *reinterpret_cast<uint2*>(l);
}

// ---------------------------------------------------------------------------
// Row squared-norm reductions (x2 also zeroes rowsum)
// ---------------------------------------------------------------------------
template <int DIM, bool IS_X>
__global__ void norm_kernel(const float* __restrict__ P) {
    int row = blockIdx.x;
    const float4* p = reinterpret_cast<const float4*>(P + (size_t)row * DIM);
    float s = 0.f;
    for (int i = threadIdx.x; i < DIM / 4; i += blockDim.x) {
        float4 v = p[i];
        s += v.x * v.x + v.y * v.y + v.z * v.z + v.w * v.w;
    }
    #pragma unroll
    for (int o = 16; o; o >>= 1) s += __shfl_xor_sync(0xffffffffu, s, o);
    __shared__ float ws[8];
    if ((threadIdx.x & 31) == 0) ws[threadIdx.x >> 5] = s;
    __syncthreads();
    if (threadIdx.x == 0) {
        float t = 0.f;
        #pragma unroll
        for (int i = 0; i < 8; i++) t += ws[i];
        if (IS_X) { g_x2[row] = t; g_rowsum[row] = 0.f; }
        else      { g_c2[row] = t; }
    }
}

// ---------------------------------------------------------------------------
// HMMA GEMM, 128x128 CTA tile, 8 warps (warp tile 64x32), K-chunk 32,
// cp.async double-buffered, 2 CTAs/SM. 3-pass bf16 hi/lo.
// A fragments resident per ks; B fragments streamed per n-pair;
// pass-major MMA order (HH.., HL.., LH..) to break accumulator RAW chains.
// ---------------------------------------------------------------------------
template <int KDIM, int MODE>
__global__ __launch_bounds__(256, 2) void gemm_mma_kernel(
    const __nv_bfloat16* __restrict__ Ahi, const __nv_bfloat16* __restrict__ Alo,
    const __nv_bfloat16* __restrict__ Bhi, const __nv_bfloat16* __restrict__ Blo,
    const float* __restrict__ beta, const float* __restrict__ bias,
    float* __restrict__ out)
{
    extern __shared__ char smem[];
    const uint32_t sb = smem_u32(smem);
    const int tid = threadIdx.x;
    const int w = tid >> 5, lane = tid & 31;
    const int warp_m = w >> 2, warp_n = w & 3;
    const int bx = blockIdx.x, by = blockIdx.y;

    // ---- loader assignment: 4 parts x 64 threads ----
    const int part = tid >> 6;
    const int l6 = tid & 63;
    const int row0 = l6 >> 2;        // 0..15
    const int gg = l6 & 3;           // 16B granule in 64B of row data
    const __nv_bfloat16* srcBase =
        (part == 0) ? Ahi : (part == 1) ? Alo : (part == 2) ? Bhi : Blo;
    const int rbase = (part < 2) ? by * 128 : bx * 128;
    const __nv_bfloat16* src0 = srcBase + (size_t)(rbase + row0) * KDIM + gg * 8;
    const uint32_t dst0 = sb + part * PART_BYTES + row0 * ROWB + gg * 16;

    float acc[4][4][4];
    #pragma unroll
    for (int mt = 0; mt < 4; mt++)
        #pragma unroll
        for (int nt = 0; nt < 4; nt++)
            #pragma unroll
            for (int q = 0; q < 4; q++) acc[mt][nt][q] = 0.f;

    constexpr int NCH = KDIM / 32;

    // issue chunk 0
    {
        #pragma unroll
        for (int j = 0; j < 8; j++)
            cp16(dst0 + j * 16 * ROWB, src0 + (size_t)(j * 16) * KDIM);
        CP_COMMIT();
    }

    const uint32_t aoff = (uint32_t)(warp_m * 64 + (lane & 15)) * ROWB +
                          (uint32_t)((lane >> 4) << 3) * 2;
    const uint32_t boff = (uint32_t)(warp_n * 32 + (lane & 7) + ((lane >> 4) << 3)) * ROWB +
                          (uint32_t)(lane & 8) * 2;

    for (int c = 0; c < NCH; c++) {
        if (c + 1 < NCH) {
            const __nv_bfloat16* s = src0 + (size_t)(c + 1) * 32;
            const uint32_t d = dst0 + ((c + 1) & 1) * BUF_BYTES;
            #pragma unroll
            for (int j = 0; j < 8; j++)
                cp16(d + j * 16 * ROWB, s + (size_t)(j * 16) * KDIM);
            CP_COMMIT();
            cp_wait<1>();
        } else {
            cp_wait<0>();
        }
        __syncthreads();

        const uint32_t bufb = sb + (c & 1) * BUF_BYTES;
        #pragma unroll
        for (int ks = 0; ks < 2; ks++) {
            const uint32_t kso = ks * 32;   // 16 bf16 = 32 bytes
            // A fragments resident for this ks
            uint32_t AH[4][4], AL[4][4];
            #pragma unroll
            for (int mt = 0; mt < 4; mt++) {
                ldsm_x4(AH[mt][0], AH[mt][1], AH[mt][2], AH[mt][3],
                        bufb + aoff + kso + mt * 16 * ROWB);
                ldsm_x4(AL[mt][0], AL[mt][1], AL[mt][2], AL[mt][3],
                        bufb + PART_BYTES + aoff + kso + mt * 16 * ROWB);
            }
            // B streamed per n-pair (2 nt tiles per ldsm.x4)
            #pragma unroll
            for (int np = 0; np < 2; np++) {
                uint32_t BH[2][2], BL[2][2];
                {
                    uint32_t r0, r1, r2, r3;
                    ldsm_x4(r0, r1, r2, r3,
                            bufb + 2 * PART_BYTES + boff + kso + np * 16 * ROWB);
                    BH[0][0] = r0; BH[0][1] = r1; BH[1][0] = r2; BH[1][1] = r3;
                    ldsm_x4(r0, r1, r2, r3,
                            bufb + 3 * PART_BYTES + boff + kso + np * 16 * ROWB);
                    BL[0][0] = r0; BL[0][1] = r1; BL[1][0] = r2; BL[1][1] = r3;
                }
                // pass-major: HH x8, HL x8, LH x8 (deps 8 apart)
                #pragma unroll
                for (int mt = 0; mt < 4; mt++)
                    #pragma unroll
                    for (int q = 0; q < 2; q++)
                        mma16816(acc[mt][np * 2 + q], AH[mt], BH[q]);
                #pragma unroll
                for (int mt = 0; mt < 4; mt++)
                    #pragma unroll
                    for (int q = 0; q < 2; q++)
                        mma16816(acc[mt][np * 2 + q], AH[mt], BL[q]);
                #pragma unroll
                for (int mt = 0; mt < 4; mt++)
                    #pragma unroll
                    for (int q = 0; q < 2; q++)
                        mma16816(acc[mt][np * 2 + q], AL[mt], BH[q]);
            }
        }
        __syncthreads();
    }

    // ------------------------------ epilogue -------------------------------
    const int lr = lane >> 2;
    const int lc = (lane & 3) * 2;

    if (MODE == 0) {
        #pragma unroll
        for (int mt = 0; mt < 4; mt++) {
            #pragma unroll
            for (int h = 0; h < 2; h++) {
                const int row = by * 128 + warp_m * 64 + mt * 16 + h * 8 + lr;
                const float x2v = g_x2[row];
                float rsum = 0.f;
                #pragma unroll
                for (int nt = 0; nt < 4; nt++) {
                    const int col = bx * 128 + warp_n * 32 + nt * 8 + lc;
                    const float d0 = acc[mt][nt][h * 2 + 0];
                    const float d1 = acc[mt][nt][h * 2 + 1];
                    float sq0 = x2v + g_c2[col]     - 2.f * d0;
                    float sq1 = x2v + g_c2[col + 1] - 2.f * d1;
                    float v0 = __expf(-beta[col]     * sqrtf(fmaxf(sq0, 0.f)));
                    float v1 = __expf(-beta[col + 1] * sqrtf(fmaxf(sq1, 0.f)));
                    rsum += v0 + v1;
                    __nv_bfloat16 h0 = __float2bfloat16(v0);
                    __nv_bfloat16 h1 = __float2bfloat16(v1);
                    __nv_bfloat16 l0 = __float2bfloat16(v0 - __bfloat162float(h0));
                    __nv_bfloat16 l1 = __float2bfloat16(v1 - __bfloat162float(h1));
                    uint32_t hp = (uint32_t)__bfloat16_as_ushort(h0) |
                                  ((uint32_t)__bfloat16_as_ushort(h1) << 16);
                    uint32_t lp = (uint32_t)__bfloat16_as_ushort(l0) |
                                  ((uint32_t)__bfloat16_as_ushort(l1) << 16);
                    *reinterpret_cast<uint32_t*>(&g_ahi[(size_t)row * C_ + col]) = hp;
                    *reinterpret_cast<uint32_t*>(&g_alo[(size_t)row * C_ + col]) = lp;
                }
                rsum += __shfl_xor_sync(0xffffffffu, rsum, 1);
                rsum += __shfl_xor_sync(0xffffffffu, rsum, 2);
                if ((lane & 3) == 0) atomicAdd(&g_rowsum[row], rsum);
            }
        }
    } else {
        #pragma unroll
        for (int mt = 0; mt < 4; mt++) {
            #pragma unroll
            for (int h = 0; h < 2; h++) {
                const int row = by * 128 + warp_m * 64 + mt * 16 + h * 8 + lr;
                const float inv = 1.0f / g_rowsum[row];
                #pragma unroll
                for (int nt = 0; nt < 4; nt++) {
                    const int col = bx * 128 + warp_n * 32 + nt * 8 + lc;
                    if (col < K_) {
                        float2 bb = *reinterpret_cast<const float2*>(&bias[col]);
                        float2 o;
                        o.x = acc[mt][nt][h * 2 + 0] * inv + bb.x;
                        o.y = acc[mt][nt][h * 2 + 1] * inv + bb.y;
                        *reinterpret_cast<float2*>(&out[(size_t)row * K_ + col]) = o;
                    }
                }
            }
        }
    }
}

// ---------------------------------------------------------------------------
extern "C" void kernel_launch(void* const* d_in, const int* in_sizes, int n_in,
                              void* d_out, int out_size) {
    const float* x       = (const float*)d_in[0];
    const float* centers = (const float*)d_in[1];
    const float* beta    = (const float*)d_in[2];
    const float* W       = (const float*)d_in[3];
    const float* bias    = (const float*)d_in[4];
    float* out = (float*)d_out;

    __nv_bfloat16 *xhi, *xlo, *chi, *clo, *ahi, *alo, *whi, *wlo;
    cudaGetSymbolAddress((void**)&xhi, g_xhi);
    cudaGetSymbolAddress((void**)&xlo, g_xlo);
    cudaGetSymbolAddress((void**)&chi, g_chi);
    cudaGetSymbolAddress((void**)&clo, g_clo);
    cudaGetSymbolAddress((void**)&ahi, g_ahi);
    cudaGetSymbolAddress((void**)&alo, g_alo);
    cudaGetSymbolAddress((void**)&whi, g_Whi);
    cudaGetSymbolAddress((void**)&wlo, g_Wlo);

    cudaFuncSetAttribute(gemm_mma_kernel<D_, 0>,
                         cudaFuncAttributeMaxDynamicSharedMemorySize, GEMM_SMEM);
    cudaFuncSetAttribute(gemm_mma_kernel<C_, 1>,
                         cudaFuncAttributeMaxDynamicSharedMemorySize, GEMM_SMEM);

    {
        int n4 = B_ * D_ / 4;
        split_kernel<<<(n4 + 255) / 256, 256>>>(x, xhi, xlo, n4);
    }
    {
        int n4 = C_ * D_ / 4;
        split_kernel<<<(n4 + 255) / 256, 256>>>(centers, chi, clo, n4);
    }
    {
        int n4 = KPAD_ * C_ / 4;
        splitW_kernel<<<(n4 + 255) / 256, 256>>>(W);
    }
    norm_kernel<D_, true><<<B_, 256>>>(x);
    norm_kernel<D_, false><<<C_, 256>>>(centers);

    dim3 g1(C_ / 128, B_ / 128);            // (32, 64)
    gemm_mma_kernel<D_, 0><<<g1, 256, GEMM_SMEM>>>(xhi, xlo, chi, clo,
                                                   beta, bias, out);

    dim3 g2(KPAD_ / 128, B_ / 128);         // (8, 64)
    gemm_mma_kernel<C_, 1><<<g2, 256, GEMM_SMEM>>>(ahi, alo, whi, wlo,
                                                   beta, bias, out);
}

// round 5
// speedup vs baseline: 2.6972x; 1.5539x over previous
#include <cuda_runtime.h>
#include <cuda_bf16.h>
#include <stdint.h>
#include <math.h>

#define B_ 8192
#define D_ 2048
#define C_ 4096
#define K_ 1000
#define KPAD_ 1024

#define PADK 40                 // smem row length in bf16 (32 data + 8 pad)
#define ROWB (PADK * 2)         // 80 bytes per row
#define PART_BYTES (128 * ROWB) // 10240
#define BUF_BYTES (4 * PART_BYTES)
#define GEMM_SMEM (2 * BUF_BYTES)

// ---------------------------------------------------------------------------
// Device scratch (no allocation allowed -> __device__ globals)
// ---------------------------------------------------------------------------
__device__ __align__(128) __nv_bfloat16 g_xhi[(size_t)B_ * D_], g_xlo[(size_t)B_ * D_];
__device__ __align__(128) __nv_bfloat16 g_chi[(size_t)C_ * D_], g_clo[(size_t)C_ * D_];
__device__ __align__(128) __nv_bfloat16 g_Whi[(size_t)KPAD_ * C_], g_Wlo[(size_t)KPAD_ * C_];
__device__ __align__(128) __nv_bfloat16 g_ahi[(size_t)B_ * C_], g_alo[(size_t)B_ * C_];
__device__ float g_x2[B_], g_c2[C_], g_rowsum[B_];

// ---------------------------------------------------------------------------
// PTX helpers (portable sm_80+: ldmatrix / mma.sync / cp.async)
// ---------------------------------------------------------------------------
__device__ __forceinline__ uint32_t smem_u32(const void* p) {
    uint32_t a;
    asm("{ .reg .u64 t; cvta.to.shared.u64 t, %1; cvt.u32.u64 %0, t; }"
        : "=r"(a) : "l"(p));
    return a;
}

__device__ __forceinline__ void ldsm_x4(uint32_t& r0, uint32_t& r1, uint32_t& r2,
                                        uint32_t& r3, uint32_t addr) {
    asm volatile("ldmatrix.sync.aligned.m8n8.x4.shared.b16 {%0,%1,%2,%3}, [%4];"
                 : "=r"(r0), "=r"(r1), "=r"(r2), "=r"(r3) : "r"(addr));
}

__device__ __forceinline__ void mma16816(float c[4], const uint32_t a[4],
                                         const uint32_t b[2]) {
    asm volatile(
        "mma.sync.aligned.m16n8k16.row.col.f32.bf16.bf16.f32 "
        "{%0,%1,%2,%3}, {%4,%5,%6,%7}, {%8,%9}, {%0,%1,%2,%3};"
        : "+f"(c[0]), "+f"(c[1]), "+f"(c[2]), "+f"(c[3])
        : "r"(a[0]), "r"(a[1]), "r"(a[2]), "r"(a[3]), "r"(b[0]), "r"(b[1]));
}

__device__ __forceinline__ void cp16(uint32_t dst, const void* src) {
    asm volatile("cp.async.cg.shared.global [%0], [%1], 16;"
                 :: "r"(dst), "l"(src) : "memory");
}
#define CP_COMMIT() asm volatile("cp.async.commit_group;" ::: "memory")
template <int N>
__device__ __forceinline__ void cp_wait() {
    asm volatile("cp.async.wait_group %0;" :: "n"(N) : "memory");
}

// ---------------------------------------------------------------------------
// Fused split + row-norm: one block per row (DIM elems), writes hi/lo bf16
// and the squared norm. IS_X also zeroes g_rowsum.
// ---------------------------------------------------------------------------
template <int DIM, bool IS_X>
__global__ void split_norm_kernel(const float* __restrict__ src,
                                  __nv_bfloat16* __restrict__ hi,
                                  __nv_bfloat16* __restrict__ lo) {
    const int row = blockIdx.x;
    const float4* p = reinterpret_cast<const float4*>(src + (size_t)row * DIM);
    float s = 0.f;
    for (int i = threadIdx.x; i < DIM / 4; i += blockDim.x) {
        float4 v = p[i];
        float f[4] = {v.x, v.y, v.z, v.w};
        s += f[0] * f[0] + f[1] * f[1] + f[2] * f[2] + f[3] * f[3];
        __nv_bfloat16 h[4], l[4];
        #pragma unroll
        for (int j = 0; j < 4; j++) {
            h[j] = __float2bfloat16(f[j]);
            l[j] = __float2bfloat16(f[j] - __bfloat162float(h[j]));
        }
        *reinterpret_cast<uint2*>(hi + (size_t)row * DIM + i * 4) =
            *reinterpret_cast<uint2*>(h);
        *reinterpret_cast<uint2*>(lo + (size_t)row * DIM + i * 4) =
            *reinterpret_cast<uint2*>(l);
    }
    #pragma unroll
    for (int o = 16; o; o >>= 1) s += __shfl_xor_sync(0xffffffffu, s, o);
    __shared__ float ws[8];
    if ((threadIdx.x & 31) == 0) ws[threadIdx.x >> 5] = s;
    __syncthreads();
    if (threadIdx.x == 0) {
        float t = 0.f;
        #pragma unroll
        for (int i = 0; i < 8; i++) t += ws[i];
        if (IS_X) { g_x2[row] = t; g_rowsum[row] = 0.f; }
        else      { g_c2[row] = t; }
    }
}

__global__ void splitW_kernel(const float* __restrict__ W) {
    int i = blockIdx.x * blockDim.x + threadIdx.x;   // over KPAD_*C_/4
    if (i >= KPAD_ * C_ / 4) return;
    int r = i >> 10;             // / (C_/4)
    int c0 = (i & 1023) * 4;
    float f[4] = {0.f, 0.f, 0.f, 0.f};
    if (r < K_) {
        float4 v = *reinterpret_cast<const float4*>(W + (size_t)r * C_ + c0);
        f[0] = v.x; f[1] = v.y; f[2] = v.z; f[3] = v.w;
    }
    __nv_bfloat16 h[4], l[4];
    #pragma unroll
    for (int j = 0; j < 4; j++) {
        h[j] = __float2bfloat16(f[j]);
        l[j] = __float2bfloat16(f[j] - __bfloat162float(h[j]));
    }
    *reinterpret_cast<uint2*>(g_Whi + (size_t)r * C_ + c0) = *reinterpret_cast<uint2*>(h);
    *reinterpret_cast<uint2*>(g_Wlo + (size_t)r * C_ + c0) = *reinterpret_cast<uint2*>(l);
}

// ---------------------------------------------------------------------------
// HMMA GEMM, 128x128 CTA tile, 8 warps (warp tile 64x32), K-chunk 32,
// cp.async double-buffered, 2 CTAs/SM. 3-pass bf16 hi/lo.
// Register-lean schedule per ks: AH+B(hi,lo) resident -> HH, HL passes;
// AL reloaded into the SAME A registers -> LH pass. ~111 live regs, no spill.
// ---------------------------------------------------------------------------
template <int KDIM, int MODE>
__global__ __launch_bounds__(256, 2) void gemm_mma_kernel(
    const __nv_bfloat16* __restrict__ Ahi, const __nv_bfloat16* __restrict__ Alo,
    const __nv_bfloat16* __restrict__ Bhi, const __nv_bfloat16* __restrict__ Blo,
    const float* __restrict__ beta, const float* __restrict__ bias,
    float* __restrict__ out)
{
    extern __shared__ char smem[];
    const uint32_t sb = smem_u32(smem);
    const int tid = threadIdx.x;
    const int w = tid >> 5, lane = tid & 31;
    const int warp_m = w >> 2, warp_n = w & 3;
    const int bx = blockIdx.x, by = blockIdx.y;

    // ---- loader assignment: 4 parts x 64 threads ----
    const int part = tid >> 6;
    const int l6 = tid & 63;
    const int row0 = l6 >> 2;        // 0..15
    const int gg = l6 & 3;           // 16B granule in 64B of row data
    const __nv_bfloat16* srcBase =
        (part == 0) ? Ahi : (part == 1) ? Alo : (part == 2) ? Bhi : Blo;
    const int rbase = (part < 2) ? by * 128 : bx * 128;
    const __nv_bfloat16* src0 = srcBase + (size_t)(rbase + row0) * KDIM + gg * 8;
    const uint32_t dst0 = sb + part * PART_BYTES + row0 * ROWB + gg * 16;

    float acc[4][4][4];
    #pragma unroll
    for (int mt = 0; mt < 4; mt++)
        #pragma unroll
        for (int nt = 0; nt < 4; nt++)
            #pragma unroll
            for (int q = 0; q < 4; q++) acc[mt][nt][q] = 0.f;

    constexpr int NCH = KDIM / 32;

    // issue chunk 0
    {
        #pragma unroll
        for (int j = 0; j < 8; j++)
            cp16(dst0 + j * 16 * ROWB, src0 + (size_t)(j * 16) * KDIM);
        CP_COMMIT();
    }

    const uint32_t aoff = (uint32_t)(warp_m * 64 + (lane & 15)) * ROWB +
                          (uint32_t)((lane >> 4) << 3) * 2;
    const uint32_t boff = (uint32_t)(warp_n * 32 + (lane & 7) + ((lane >> 4) << 3)) * ROWB +
                          (uint32_t)(lane & 8) * 2;

    for (int c = 0; c < NCH; c++) {
        if (c + 1 < NCH) {
            const __nv_bfloat16* s = src0 + (size_t)(c + 1) * 32;
            const uint32_t d = dst0 + ((c + 1) & 1) * BUF_BYTES;
            #pragma unroll
            for (int j = 0; j < 8; j++)
                cp16(d + j * 16 * ROWB, s + (size_t)(j * 16) * KDIM);
            CP_COMMIT();
            cp_wait<1>();
        } else {
            cp_wait<0>();
        }
        __syncthreads();

        const uint32_t bufb = sb + (c & 1) * BUF_BYTES;
        #pragma unroll
        for (int ks = 0; ks < 2; ks++) {
            const uint32_t kso = ks * 32;   // 16 bf16 = 32 bytes

            uint32_t A[4][4];     // reused: first AH, then AL
            uint32_t BH[4][2], BL[4][2];

            // load AH + all B fragments (hi & lo)
            #pragma unroll
            for (int mt = 0; mt < 4; mt++)
                ldsm_x4(A[mt][0], A[mt][1], A[mt][2], A[mt][3],
                        bufb + aoff + kso + mt * 16 * ROWB);
            #pragma unroll
            for (int np = 0; np < 2; np++) {
                uint32_t r0, r1, r2, r3;
                ldsm_x4(r0, r1, r2, r3,
                        bufb + 2 * PART_BYTES + boff + kso + np * 16 * ROWB);
                BH[np * 2][0] = r0; BH[np * 2][1] = r1;
                BH[np * 2 + 1][0] = r2; BH[np * 2 + 1][1] = r3;
                ldsm_x4(r0, r1, r2, r3,
                        bufb + 3 * PART_BYTES + boff + kso + np * 16 * ROWB);
                BL[np * 2][0] = r0; BL[np * 2][1] = r1;
                BL[np * 2 + 1][0] = r2; BL[np * 2 + 1][1] = r3;
            }

            // pass HH
            #pragma unroll
            for (int mt = 0; mt < 4; mt++)
                #pragma unroll
                for (int nt = 0; nt < 4; nt++)
                    mma16816(acc[mt][nt], A[mt], BH[nt]);
            // pass HL
            #pragma unroll
            for (int mt = 0; mt < 4; mt++)
                #pragma unroll
                for (int nt = 0; nt < 4; nt++)
                    mma16816(acc[mt][nt], A[mt], BL[nt]);

            // reload AL into the same registers (WAR: prior MMAs consumed A at issue)
            #pragma unroll
            for (int mt = 0; mt < 4; mt++)
                ldsm_x4(A[mt][0], A[mt][1], A[mt][2], A[mt][3],
                        bufb + PART_BYTES + aoff + kso + mt * 16 * ROWB);
            // pass LH
            #pragma unroll
            for (int mt = 0; mt < 4; mt++)
                #pragma unroll
                for (int nt = 0; nt < 4; nt++)
                    mma16816(acc[mt][nt], A[mt], BH[nt]);
        }
        __syncthreads();
    }

    // ------------------------------ epilogue -------------------------------
    const int lr = lane >> 2;
    const int lc = (lane & 3) * 2;

    if (MODE == 0) {
        #pragma unroll
        for (int mt = 0; mt < 4; mt++) {
            #pragma unroll
            for (int h = 0; h < 2; h++) {
                const int row = by * 128 + warp_m * 64 + mt * 16 + h * 8 + lr;
                const float x2v = g_x2[row];
                float rsum = 0.f;
                #pragma unroll
                for (int nt = 0; nt < 4; nt++) {
                    const int col = bx * 128 + warp_n * 32 + nt * 8 + lc;
                    const float d0 = acc[mt][nt][h * 2 + 0];
                    const float d1 = acc[mt][nt][h * 2 + 1];
                    float sq0 = x2v + g_c2[col]     - 2.f * d0;
                    float sq1 = x2v + g_c2[col + 1] - 2.f * d1;
                    float v0 = __expf(-beta[col]     * sqrtf(fmaxf(sq0, 0.f)));
                    float v1 = __expf(-beta[col + 1] * sqrtf(fmaxf(sq1, 0.f)));
                    rsum += v0 + v1;
                    __nv_bfloat16 h0 = __float2bfloat16(v0);
                    __nv_bfloat16 h1 = __float2bfloat16(v1);
                    __nv_bfloat16 l0 = __float2bfloat16(v0 - __bfloat162float(h0));
                    __nv_bfloat16 l1 = __float2bfloat16(v1 - __bfloat162float(h1));
                    uint32_t hp = (uint32_t)__bfloat16_as_ushort(h0) |
                                  ((uint32_t)__bfloat16_as_ushort(h1) << 16);
                    uint32_t lp = (uint32_t)__bfloat16_as_ushort(l0) |
                                  ((uint32_t)__bfloat16_as_ushort(l1) << 16);
                    *reinterpret_cast<uint32_t*>(&g_ahi[(size_t)row * C_ + col]) = hp;
                    *reinterpret_cast<uint32_t*>(&g_alo[(size_t)row * C_ + col]) = lp;
                }
                rsum += __shfl_xor_sync(0xffffffffu, rsum, 1);
                rsum += __shfl_xor_sync(0xffffffffu, rsum, 2);
                if ((lane & 3) == 0) atomicAdd(&g_rowsum[row], rsum);
            }
        }
    } else {
        #pragma unroll
        for (int mt = 0; mt < 4; mt++) {
            #pragma unroll
            for (int h = 0; h < 2; h++) {
                const int row = by * 128 + warp_m * 64 + mt * 16 + h * 8 + lr;
                const float inv = 1.0f / g_rowsum[row];
                #pragma unroll
                for (int nt = 0; nt < 4; nt++) {
                    const int col = bx * 128 + warp_n * 32 + nt * 8 + lc;
                    if (col < K_) {
                        float2 bb = *reinterpret_cast<const float2*>(&bias[col]);
                        float2 o;
                        o.x = acc[mt][nt][h * 2 + 0] * inv + bb.x;
                        o.y = acc[mt][nt][h * 2 + 1] * inv + bb.y;
                        *reinterpret_cast<float2*>(&out[(size_t)row * K_ + col]) = o;
                    }
                }
            }
        }
    }
}

// ---------------------------------------------------------------------------
extern "C" void kernel_launch(void* const* d_in, const int* in_sizes, int n_in,
                              void* d_out, int out_size) {
    const float* x       = (const float*)d_in[0];
    const float* centers = (const float*)d_in[1];
    const float* beta    = (const float*)d_in[2];
    const float* W       = (const float*)d_in[3];
    const float* bias    = (const float*)d_in[4];
    float* out = (float*)d_out;

    __nv_bfloat16 *xhi, *xlo, *chi, *clo, *ahi, *alo, *whi, *wlo;
    cudaGetSymbolAddress((void**)&xhi, g_xhi);
    cudaGetSymbolAddress((void**)&xlo, g_xlo);
    cudaGetSymbolAddress((void**)&chi, g_chi);
    cudaGetSymbolAddress((void**)&clo, g_clo);
    cudaGetSymbolAddress((void**)&ahi, g_ahi);
    cudaGetSymbolAddress((void**)&alo, g_alo);
    cudaGetSymbolAddress((void**)&whi, g_Whi);
    cudaGetSymbolAddress((void**)&wlo, g_Wlo);

    cudaFuncSetAttribute(gemm_mma_kernel<D_, 0>,
                         cudaFuncAttributeMaxDynamicSharedMemorySize, GEMM_SMEM);
    cudaFuncSetAttribute(gemm_mma_kernel<C_, 1>,
                         cudaFuncAttributeMaxDynamicSharedMemorySize, GEMM_SMEM);

    split_norm_kernel<D_, true><<<B_, 256>>>(x, xhi, xlo);
    split_norm_kernel<D_, false><<<C_, 256>>>(centers, chi, clo);
    {
        int n4 = KPAD_ * C_ / 4;
        splitW_kernel<<<(n4 + 255) / 256, 256>>>(W);
    }

    dim3 g1(C_ / 128, B_ / 128);            // (32, 64)
    gemm_mma_kernel<D_, 0><<<g1, 256, GEMM_SMEM>>>(xhi, xlo, chi, clo,
                                                   beta, bias, out);

    dim3 g2(KPAD_ / 128, B_ / 128);         // (8, 64)
    gemm_mma_kernel<C_, 1><<<g2, 256, GEMM_SMEM>>>(ahi, alo, whi, wlo,
                                                   beta, bias, out);
}